// round 12
// baseline (speedup 1.0000x reference)
#include <cuda_runtime.h>
#include <cuda_bf16.h>
#include <math.h>
#include <stdint.h>

// Problem constants
constexpr int NB = 8;     // batch
constexpr int NQ = 512;   // query len
constexpr int NM = 512;   // memory len
constexpr int NR = 1024;  // reference len
constexpr int NH = 16;    // heads
constexpr int NS = 64;    // size per head
constexpr int ND = 1024;  // hidden

#define ALGN __align__(16)

// bf16 split attention operands (written by projection epilogues)
__device__ ALGN __nv_bfloat16 g_QCh[(size_t)NB*NH*NQ*NS];
__device__ ALGN __nv_bfloat16 g_QCl[(size_t)NB*NH*NQ*NS];
__device__ ALGN __nv_bfloat16 g_QPh[(size_t)NB*NH*NQ*NS];
__device__ ALGN __nv_bfloat16 g_QPl[(size_t)NB*NH*NQ*NS];
__device__ ALGN __nv_bfloat16 g_KCh[(size_t)NB*NH*NR*NS];
__device__ ALGN __nv_bfloat16 g_KCl[(size_t)NB*NH*NR*NS];
__device__ ALGN __nv_bfloat16 g_KPh[(size_t)NH*NR*NS];
__device__ ALGN __nv_bfloat16 g_KPl[(size_t)NH*NR*NS];
__device__ ALGN __nv_bfloat16 g_VtH[(size_t)NB*NH*NS*NR];  // V transposed [z][s][r]
__device__ ALGN __nv_bfloat16 g_VtL[(size_t)NB*NH*NS*NR];
// attention output (bf16 split, written by fused_attn)
__device__ ALGN __nv_bfloat16 g_OH[(size_t)NB*NQ*ND];
__device__ ALGN __nv_bfloat16 g_OL[(size_t)NB*NQ*ND];

// bf16 split inputs for projections
__device__ ALGN __nv_bfloat16 g_XrefH[(size_t)NB*NR*ND];
__device__ ALGN __nv_bfloat16 g_XrefL[(size_t)NB*NR*ND];
__device__ ALGN __nv_bfloat16 g_PEH[(size_t)NR*ND];
__device__ ALGN __nv_bfloat16 g_PEL[(size_t)NR*ND];
// transposed weights Wt[c][k]: 0=Wq 1=Wkc 2=Wkp 3=Wv 4=Wo
__device__ ALGN __nv_bfloat16 g_WtH[5][(size_t)ND*ND];
__device__ ALGN __nv_bfloat16 g_WtL[5][(size_t)ND*ND];

enum { MODE_Q = 0, MODE_KC = 1, MODE_V = 2, MODE_KP = 3, MODE_OUT = 4 };

// ---------------------------------------------------------------------------
// helpers
// ---------------------------------------------------------------------------
__device__ __forceinline__ uint32_t smem_u32(const void* p) {
    uint32_t a;
    asm("{ .reg .u64 t; cvta.to.shared.u64 t, %1; cvt.u32.u64 %0, t; }"
        : "=r"(a) : "l"(p));
    return a;
}
__device__ __forceinline__ void cp16(uint32_t dst, const void* src) {
    asm volatile("cp.async.cg.shared.global [%0], [%1], 16;"
                 :: "r"(dst), "l"(src) : "memory");
}
__device__ __forceinline__ void ldsm_x4(uint32_t* r, uint32_t addr) {
    asm volatile("ldmatrix.sync.aligned.m8n8.x4.shared.b16 {%0,%1,%2,%3}, [%4];"
                 : "=r"(r[0]), "=r"(r[1]), "=r"(r[2]), "=r"(r[3]) : "r"(addr));
}
__device__ __forceinline__ void mma16816(float* c, const uint32_t* a, const uint32_t* b) {
    asm volatile(
        "mma.sync.aligned.m16n8k16.row.col.f32.bf16.bf16.f32 "
        "{%0,%1,%2,%3}, {%4,%5,%6,%7}, {%8,%9}, {%0,%1,%2,%3};"
        : "+f"(c[0]), "+f"(c[1]), "+f"(c[2]), "+f"(c[3])
        : "r"(a[0]), "r"(a[1]), "r"(a[2]), "r"(a[3]), "r"(b[0]), "r"(b[1]));
}
#define SWZ64(x)  ((x) ^ (((x) >> 3) & 0x30))
#define SWZ128(x) ((x) ^ (((x) >> 3) & 0x70))

__device__ __forceinline__ void split1(float v, __nv_bfloat16& h, __nv_bfloat16& l) {
    h = __float2bfloat16(v);
    l = __float2bfloat16(v - __bfloat162float(h));
}
__device__ __forceinline__ void store_split2(__nv_bfloat16* ph, __nv_bfloat16* pl,
                                             float a, float b) {
    __nv_bfloat162 hh, ll;
    hh.x = __float2bfloat16(a);
    ll.x = __float2bfloat16(a - __bfloat162float(hh.x));
    hh.y = __float2bfloat16(b);
    ll.y = __float2bfloat16(b - __bfloat162float(hh.y));
    *(__nv_bfloat162*)ph = hh;
    *(__nv_bfloat162*)pl = ll;
}
__device__ __forceinline__ uint32_t pack_split(float a, float b, uint32_t& lo) {
    __nv_bfloat162 hh, ll;
    hh.x = __float2bfloat16(a);
    ll.x = __float2bfloat16(a - __bfloat162float(hh.x));
    hh.y = __float2bfloat16(b);
    ll.y = __float2bfloat16(b - __bfloat162float(hh.y));
    lo = *(uint32_t*)&ll;
    return *(uint32_t*)&hh;
}

// ---------------------------------------------------------------------------
// Conversion kernels
// ---------------------------------------------------------------------------
__global__ void conv_xref(const float* __restrict__ qry, const float* __restrict__ mem) {
    const int row = blockIdx.x;
    const int b = row >> 10, r = row & 1023;
    const float* src = (r < NM) ? mem + ((size_t)(b * NM + r)) * ND
                                : qry + ((size_t)(b * NQ + (r - NM))) * ND;
    const int c = threadIdx.x * 4;
    float4 v = *(const float4*)(src + c);
    const size_t o = (size_t)row * ND + c;
    split1(v.x, g_XrefH[o+0], g_XrefL[o+0]);
    split1(v.y, g_XrefH[o+1], g_XrefL[o+1]);
    split1(v.z, g_XrefH[o+2], g_XrefL[o+2]);
    split1(v.w, g_XrefH[o+3], g_XrefL[o+3]);
}

__global__ void conv_pe(const float* __restrict__ src) {
    const size_t i = (size_t)blockIdx.x * blockDim.x + threadIdx.x;
    split1(src[i], g_PEH[i], g_PEL[i]);
}

template <int WID>
__global__ void conv_wt(const float* __restrict__ W) {
    __shared__ float tile[32][33];
    const int c0 = blockIdx.x * 32, k0 = blockIdx.y * 32;
    const int tx = threadIdx.x, ty = threadIdx.y;  // 32 x 8
    for (int i = ty; i < 32; i += 8)
        tile[i][tx] = W[(size_t)(k0 + i) * ND + c0 + tx];
    __syncthreads();
    for (int i = ty; i < 32; i += 8) {
        float v = tile[tx][i];
        __nv_bfloat16 h, l;
        split1(v, h, l);
        const size_t o = (size_t)(c0 + i) * ND + k0 + tx;
        g_WtH[WID][o] = h;
        g_WtL[WID][o] = l;
    }
}

// ---------------------------------------------------------------------------
// Split-bf16 mma.sync projection GEMM (3-pass) — unchanged (passing R11).
// ---------------------------------------------------------------------------
constexpr int TILEB  = 128 * 64;
constexpr int STAGEB = 4 * TILEB;
constexpr int GSMEM  = 2 * STAGEB + 1024;
constexpr int NCHUNK = ND / 32;

template <int MODE>
__global__ __launch_bounds__(256)
void mma_gemm(const float* __restrict__ cb, const float* __restrict__ pb,
              float* __restrict__ outp)
{
    extern __shared__ char dsm[];
    const uint32_t dyn_u32 = smem_u32(dsm);
    const uint32_t base = (dyn_u32 + 1023u) & ~1023u;
    float* stg = reinterpret_cast<float*>(dsm + (base - dyn_u32));

    const int t = threadIdx.x;
    const int wid = t >> 5, lane = t & 31;
    const int n0 = blockIdx.x * 128;
    const int m0 = blockIdx.y * 128;
    const int arow0 = (MODE == MODE_Q) ? ((m0 >> 9) * 1024 + 512 + (m0 & 511)) : m0;

    const __nv_bfloat16 *Ah, *Al, *Bh, *Bl;
    if (MODE == MODE_Q)       { Ah = g_XrefH; Al = g_XrefL; Bh = g_WtH[0]; Bl = g_WtL[0]; }
    else if (MODE == MODE_KC) { Ah = g_XrefH; Al = g_XrefL; Bh = g_WtH[1]; Bl = g_WtL[1]; }
    else if (MODE == MODE_KP) { Ah = g_PEH;   Al = g_PEL;   Bh = g_WtH[2]; Bl = g_WtL[2]; }
    else if (MODE == MODE_V)  { Ah = g_XrefH; Al = g_XrefL; Bh = g_WtH[3]; Bl = g_WtL[3]; }
    else                      { Ah = g_OH;    Al = g_OL;    Bh = g_WtH[4]; Bl = g_WtL[4]; }

    const int s0 = t;
    const int mseg0 = s0 >> 2, cseg0 = s0 & 3;
    const int s1 = t + 256;
    const int mseg1 = s1 >> 2, cseg1 = s1 & 3;

    auto load_stage = [&](int chunk, int buf) {
        const uint32_t sb = base + buf * STAGEB;
        const int kbyte = chunk * 64;
        {
            const char* a0 = (const char*)(Ah + (size_t)(arow0 + mseg0) * ND) + kbyte + cseg0 * 16;
            const char* a1 = (const char*)(Al + (size_t)(arow0 + mseg0) * ND) + kbyte + cseg0 * 16;
            const char* b0 = (const char*)(Bh + (size_t)(n0 + mseg0) * ND) + kbyte + cseg0 * 16;
            const char* b1 = (const char*)(Bl + (size_t)(n0 + mseg0) * ND) + kbyte + cseg0 * 16;
            const uint32_t sw = SWZ64((uint32_t)(mseg0 * 64 + cseg0 * 16));
            cp16(sb + 0 * TILEB + sw, a0);
            cp16(sb + 1 * TILEB + sw, a1);
            cp16(sb + 2 * TILEB + sw, b0);
            cp16(sb + 3 * TILEB + sw, b1);
        }
        {
            const char* a0 = (const char*)(Ah + (size_t)(arow0 + mseg1) * ND) + kbyte + cseg1 * 16;
            const char* a1 = (const char*)(Al + (size_t)(arow0 + mseg1) * ND) + kbyte + cseg1 * 16;
            const char* b0 = (const char*)(Bh + (size_t)(n0 + mseg1) * ND) + kbyte + cseg1 * 16;
            const char* b1 = (const char*)(Bl + (size_t)(n0 + mseg1) * ND) + kbyte + cseg1 * 16;
            const uint32_t sw = SWZ64((uint32_t)(mseg1 * 64 + cseg1 * 16));
            cp16(sb + 0 * TILEB + sw, a0);
            cp16(sb + 1 * TILEB + sw, a1);
            cp16(sb + 2 * TILEB + sw, b0);
            cp16(sb + 3 * TILEB + sw, b1);
        }
        asm volatile("cp.async.commit_group;" ::: "memory");
    };

    const int wm = wid >> 1;
    const int wn = wid & 1;
    const int mbase = wm * 32;
    const int nbase = wn * 64;

    const int tle = lane >> 3;
    const int rin = lane & 7;
    const int a_moff = rin + (tle & 1) * 8;
    const int a_koff = (tle >> 1) * 16;
    const int b_noff = (tle < 2) ? rin : (rin + 8);
    const int b_koff = (tle & 1) * 16;

    float acc[2][8][4];
    #pragma unroll
    for (int i = 0; i < 2; i++)
        #pragma unroll
        for (int j = 0; j < 8; j++)
            #pragma unroll
            for (int k = 0; k < 4; k++) acc[i][j][k] = 0.f;

    auto compute_stage = [&](int buf) {
        const uint32_t sb = base + buf * STAGEB;
        #pragma unroll
        for (int ks = 0; ks < 2; ks++) {
            uint32_t ah[2][4], al[2][4], bh[4][4], bl[4][4];
            #pragma unroll
            for (int i = 0; i < 2; i++) {
                const uint32_t off = SWZ64((uint32_t)((mbase + 16 * i + a_moff) * 64 + ks * 32 + a_koff));
                ldsm_x4(ah[i], sb + 0 * TILEB + off);
                ldsm_x4(al[i], sb + 1 * TILEB + off);
            }
            #pragma unroll
            for (int jp = 0; jp < 4; jp++) {
                const uint32_t off = SWZ64((uint32_t)((nbase + 16 * jp + b_noff) * 64 + ks * 32 + b_koff));
                ldsm_x4(bh[jp], sb + 2 * TILEB + off);
                ldsm_x4(bl[jp], sb + 3 * TILEB + off);
            }
            #pragma unroll
            for (int i = 0; i < 2; i++) {
                #pragma unroll
                for (int j = 0; j < 8; j++)
                    mma16816(acc[i][j], ah[i], &bh[j >> 1][(j & 1) * 2]);
                #pragma unroll
                for (int j = 0; j < 8; j++)
                    mma16816(acc[i][j], ah[i], &bl[j >> 1][(j & 1) * 2]);
                #pragma unroll
                for (int j = 0; j < 8; j++)
                    mma16816(acc[i][j], al[i], &bh[j >> 1][(j & 1) * 2]);
            }
        }
    };

    load_stage(0, 0);
    for (int c = 0; c < NCHUNK; c++) {
        const int buf = c & 1;
        if (c + 1 < NCHUNK) {
            load_stage(c + 1, buf ^ 1);
            asm volatile("cp.async.wait_group 1;" ::: "memory");
        } else {
            asm volatile("cp.async.wait_group 0;" ::: "memory");
        }
        __syncthreads();
        compute_stage(buf);
        __syncthreads();
    }

    const int lr = lane >> 2;
    const int lc = (lane & 3) * 2;
    for (int p = 0; p < 2; p++) {
        if ((wm >> 1) == p) {
            const int rb = mbase - p * 64;
            #pragma unroll
            for (int i = 0; i < 2; i++) {
                #pragma unroll
                for (int j = 0; j < 8; j++) {
                    const int rr = rb + 16 * i + lr;
                    const int cc = nbase + 8 * j + lc;
                    *(float2*)&stg[rr * 132 + cc]       = make_float2(acc[i][j][0], acc[i][j][1]);
                    *(float2*)&stg[(rr + 8) * 132 + cc] = make_float2(acc[i][j][2], acc[i][j][3]);
                }
            }
        }
        __syncthreads();
        if (MODE == MODE_V) {
            const int c = t >> 1;
            const int rseg = (t & 1) * 32;
            const int b = m0 >> 10;
            const int h = (n0 + c) >> 6, sO = (n0 + c) & 63;
            const int rglob0 = (m0 & 1023) + 64 * p + rseg;
            const size_t vo = (((size_t)(b * NH + h)) * NS + sO) * NR + rglob0;
            #pragma unroll 8
            for (int rl = 0; rl < 32; rl += 2) {
                store_split2(&g_VtH[vo + rl], &g_VtL[vo + rl],
                             stg[(rseg + rl) * 132 + c], stg[(rseg + rl + 1) * 132 + c]);
            }
        } else {
            const int rl = t >> 2;
            const int quad = t & 3;
            const int grow = m0 + 64 * p + rl;
            const int cq = quad * 32;
            const float* sp = stg + rl * 132 + cq;
            if (MODE == MODE_Q) {
                const int b = grow >> 9, q = grow & 511;
                const int h = (n0 + cq) >> 6, sO = (n0 + cq) & 63;
                const size_t o = (((size_t)(b * NH + h)) * NQ + q) * NS + sO;
                const float* cbp = cb + n0 + cq;
                const float* pbp = pb + n0 + cq;
                #pragma unroll
                for (int j = 0; j < 32; j += 2) {
                    const float v0 = sp[j], v1 = sp[j + 1];
                    store_split2(&g_QCh[o + j], &g_QCl[o + j], v0 + cbp[j], v1 + cbp[j + 1]);
                    store_split2(&g_QPh[o + j], &g_QPl[o + j], v0 + pbp[j], v1 + pbp[j + 1]);
                }
            } else if (MODE == MODE_KC) {
                const int b = grow >> 10, r = grow & 1023;
                const int h = (n0 + cq) >> 6, sO = (n0 + cq) & 63;
                const size_t o = (((size_t)(b * NH + h)) * NR + r) * NS + sO;
                #pragma unroll
                for (int j = 0; j < 32; j += 2)
                    store_split2(&g_KCh[o + j], &g_KCl[o + j], sp[j], sp[j + 1]);
            } else if (MODE == MODE_KP) {
                const int h = (n0 + cq) >> 6, sO = (n0 + cq) & 63;
                const size_t o = ((size_t)h * NR + grow) * NS + sO;
                #pragma unroll
                for (int j = 0; j < 32; j += 2)
                    store_split2(&g_KPh[o + j], &g_KPl[o + j], sp[j], sp[j + 1]);
            } else {
                float* d1 = outp + (size_t)grow * ND + n0 + cq;
                #pragma unroll
                for (int j = 0; j < 32; j += 4)
                    *(float4*)(d1 + j) = make_float4(sp[j], sp[j+1], sp[j+2], sp[j+3]);
            }
        }
        __syncthreads();
    }
}

// ---------------------------------------------------------------------------
// fused_attn: 8-warp CTA over a 128-row q-tile (two 64-row subtiles sharing
// KC/V/KP streams). Warps 0-3 = subtile L, 4-7 = subtile H; each warp owns
// 16 q-rows and runs the full R11 per-warp pipeline (PP tile + content +
// online softmax + PV). KP ring = 4 slots; per-subtile 2-bank PP cache.
// Q smem is overlaid on the PP region (Q only read in prologue).
// ---------------------------------------------------------------------------
constexpr int F_T    = 8192;                 // one 64x128B tile
constexpr int OFF_KC = 0;                    // 2 bufs x (h,l) = 4 tiles
constexpr int OFF_V  = 4 * F_T;              // 4 tiles
constexpr int OFF_KP = 8 * F_T;              // 4 slots x (h,l) = 8 tiles
constexpr int OFF_PP = 16 * F_T;             // 2 subtiles x 2 banks x 64x66 fp32
constexpr int OFF_Q  = OFF_PP;               // overlay (prologue only)
constexpr int PPS    = 66;
constexpr int PPBANK = 64 * PPS;             // floats per bank
constexpr int FSMEM  = OFF_PP + 4 * PPBANK * 4 + 1024;
static_assert(OFF_Q + 8 * F_T <= OFF_PP + 4 * PPBANK * 4, "Q overlay fits in PP");

__global__ __launch_bounds__(256)
void fused_attn()
{
    extern __shared__ char fsm[];
    const uint32_t raw = smem_u32(fsm);
    const uint32_t base = (raw + 1023u) & ~1023u;
    float* sPPall = reinterpret_cast<float*>(fsm + (base - raw) + OFF_PP);

    const int qt2 = blockIdx.x;            // 0..3 (128-row q-tile)
    const int z   = blockIdx.y;
    const int b = z >> 4, h = z & 15;
    const int nt_h = 2 * qt2 + 10;         // total r-tile iterations
    const int t = threadIdx.x;
    const int wid = t >> 5, lane = t & 31;
    const int s  = wid >> 2;               // subtile 0 (L) / 1 (H)
    const int wi = wid & 3;
    const int mrow = wi * 16;
    const int q0s = 128 * qt2 + 64 * s;    // subtile q base
    const int nt_s = 2 * qt2 + 9 + s;      // active iterations for this subtile
    const int tjn  = (s ? 7 : 8) - 2 * qt2; // new PP tile index = tjn + c

    float* sPP = sPPall + s * 2 * PPBANK;  // this subtile's 2 PP banks

    const char* KCh = (const char*)(g_KCh + (size_t)z * NR * NS);
    const char* KCl = (const char*)(g_KCl + (size_t)z * NR * NS);
    const char* KPh = (const char*)(g_KPh + (size_t)h * NR * NS);
    const char* KPl = (const char*)(g_KPl + (size_t)h * NR * NS);
    const char* Vh  = (const char*)(g_VtH + (size_t)z * NS * NR);
    const char* Vl  = (const char*)(g_VtL + (size_t)z * NS * NR);

    auto load_kcv = [&](int c, int buf) {
        const uint32_t kb = base + OFF_KC + buf * 2 * F_T;
        const uint32_t vb = base + OFF_V  + buf * 2 * F_T;
        #pragma unroll
        for (int i = 0; i < 2; i++) {
            const int idx = t + 256 * i;         // 0..511
            const int row = idx >> 3, c16 = idx & 7;
            const uint32_t sw = SWZ128((uint32_t)(row * 128 + c16 * 16));
            const size_t kco = (size_t)(c * 64 + row) * 128 + c16 * 16;
            cp16(kb + sw,       KCh + kco);
            cp16(kb + F_T + sw, KCl + kco);
            const size_t vo = (size_t)row * (NR * 2) + (size_t)c * 128 + c16 * 16;
            cp16(vb + sw,       Vh + vo);
            cp16(vb + F_T + sw, Vl + vo);
        }
    };
    auto load_kp = [&](int tj) {
        const uint32_t kb = base + OFF_KP + (tj & 3) * 2 * F_T;
        #pragma unroll
        for (int i = 0; i < 2; i++) {
            const int idx = t + 256 * i;
            const int row = idx >> 3, c16 = idx & 7;
            int k = tj * 64 + row;
            if (k > 1023) k = 1023;              // clamped rows feed masked lanes only
            const uint32_t sw = SWZ128((uint32_t)(row * 128 + c16 * 16));
            cp16(kb + sw,       KPh + (size_t)k * 128 + c16 * 16);
            cp16(kb + F_T + sw, KPl + (size_t)k * 128 + c16 * 16);
        }
    };

    // ---- prologue loads: 8 Q tiles + KC/V buf0 + KP tiles tjn_h..tjn_h+2 ----
    {
        const char* const qarr[4] = {(const char*)g_QCh, (const char*)g_QCl,
                                     (const char*)g_QPh, (const char*)g_QPl};
        const size_t qb0 = ((size_t)z * NQ + 128 * qt2) * NS * 2;
        #pragma unroll
        for (int i = 0; i < 16; i++) {
            const int idx = t + 256 * i;
            const int tl = idx >> 9;             // 0..7
            const int ch = idx & 511;
            const int row = ch >> 3, c16 = ch & 7;
            const int ss = tl >> 2, arr = tl & 3;
            cp16(base + OFF_Q + tl * F_T + SWZ128((uint32_t)(row * 128 + c16 * 16)),
                 qarr[arr] + qb0 + (size_t)ss * 64 * NS * 2 + (size_t)row * 128 + c16 * 16);
        }
    }
    load_kcv(0, 0);
    load_kp(6 - 2 * qt2);
    load_kp(7 - 2 * qt2);
    load_kp(8 - 2 * qt2);
    asm volatile("cp.async.commit_group;" ::: "memory");
    asm volatile("cp.async.wait_group 0;" ::: "memory");
    __syncthreads();

    const int tle = lane >> 3;
    const int rin = lane & 7;
    const int a_moff = rin + (tle & 1) * 8;
    const int a_koff = (tle >> 1) * 16;
    const int b_noff = (tle < 2) ? rin : (rin + 8);
    const int b_koff = (tle & 1) * 16;
    const int r_ = lane >> 2;
    const int c2 = (lane & 3) * 2;
    const int row0 = mrow + r_;           // subtile-local row
    const int row1 = row0 + 8;

    // preload Q a-frags (persistent; from this subtile's tiles)
    uint32_t qch[4][4], qcl[4][4], qph[4][4], qpl[4][4];
    #pragma unroll
    for (int ks = 0; ks < 4; ks++) {
        const uint32_t off = SWZ128((uint32_t)((mrow + a_moff) * 128 + ks * 32 + a_koff));
        const uint32_t qb = base + OFF_Q + (s * 4) * F_T;
        ldsm_x4(qch[ks], qb + 0 * F_T + off);
        ldsm_x4(qcl[ks], qb + 1 * F_T + off);
        ldsm_x4(qph[ks], qb + 2 * F_T + off);
        ldsm_x4(qpl[ks], qb + 3 * F_T + off);
    }
    __syncthreads();   // Q frags done before PP overwrites the overlaid region

    // compute one PP tile (3-pass) from KP slot tj&3 into PP bank tj&1
    auto pp_tile = [&](int tj) {
        const uint32_t kb = base + OFF_KP + (tj & 3) * 2 * F_T;
        float pa[8][4];
        #pragma unroll
        for (int j = 0; j < 8; j++)
            #pragma unroll
            for (int e = 0; e < 4; e++) pa[j][e] = 0.f;
        #pragma unroll
        for (int ks = 0; ks < 4; ks++) {
            uint32_t bh[4][4], bl[4][4];
            #pragma unroll
            for (int jp = 0; jp < 4; jp++) {
                const uint32_t off = SWZ128((uint32_t)((16 * jp + b_noff) * 128 + ks * 32 + b_koff));
                ldsm_x4(bh[jp], kb + off);
                ldsm_x4(bl[jp], kb + F_T + off);
            }
            #pragma unroll
            for (int j = 0; j < 8; j++)
                mma16816(pa[j], qph[ks], &bh[j >> 1][(j & 1) * 2]);
            #pragma unroll
            for (int j = 0; j < 8; j++)
                mma16816(pa[j], qph[ks], &bl[j >> 1][(j & 1) * 2]);
            #pragma unroll
            for (int j = 0; j < 8; j++)
                mma16816(pa[j], qpl[ks], &bh[j >> 1][(j & 1) * 2]);
        }
        float* bw = sPP + (tj & 1) * PPBANK;
        #pragma unroll
        for (int j = 0; j < 8; j++) {
            const int col = 8 * j + c2;
            *(float2*)&bw[row0 * PPS + col] = make_float2(pa[j][0], pa[j][1]);
            *(float2*)&bw[row1 * PPS + col] = make_float2(pa[j][2], pa[j][3]);
        }
    };

    // prologue PP: each subtile's initial lower-window tile = tjn - 1
    pp_tile(tjn - 1);

    float m0 = -1e30f, m1 = -1e30f, s0 = 0.f, s1 = 0.f;
    float acc_o[8][4];
    #pragma unroll
    for (int j = 0; j < 8; j++)
        #pragma unroll
        for (int e = 0; e < 4; e++) acc_o[j][e] = 0.f;

    for (int c = 0; c < nt_h; c++) {
        const int buf = c & 1;
        if (c + 1 < nt_h) {
            load_kcv(c + 1, buf ^ 1);
            load_kp(9 - 2 * qt2 + c);
            asm volatile("cp.async.commit_group;" ::: "memory");
            asm volatile("cp.async.wait_group 1;" ::: "memory");
        } else {
            asm volatile("cp.async.wait_group 0;" ::: "memory");
        }
        __syncthreads();

        const bool act = (c < nt_s);
        float cl[8][4];
        if (act) {
            // new positional tile for this subtile
            pp_tile(tjn + c);

            // content logits (3-pass, K=64)
            #pragma unroll
            for (int j = 0; j < 8; j++)
                #pragma unroll
                for (int e = 0; e < 4; e++) cl[j][e] = 0.f;
            const uint32_t kb = base + OFF_KC + buf * 2 * F_T;
            #pragma unroll
            for (int ks = 0; ks < 4; ks++) {
                uint32_t bh[4][4], bl[4][4];
                #pragma unroll
                for (int jp = 0; jp < 4; jp++) {
                    const uint32_t off = SWZ128((uint32_t)((16 * jp + b_noff) * 128 + ks * 32 + b_koff));
                    ldsm_x4(bh[jp], kb + off);
                    ldsm_x4(bl[jp], kb + F_T + off);
                }
                #pragma unroll
                for (int j = 0; j < 8; j++)
                    mma16816(cl[j], qch[ks], &bh[j >> 1][(j & 1) * 2]);
                #pragma unroll
                for (int j = 0; j < 8; j++)
                    mma16816(cl[j], qch[ks], &bl[j >> 1][(j & 1) * 2]);
                #pragma unroll
                for (int j = 0; j < 8; j++)
                    mma16816(cl[j], qcl[ks], &bh[j >> 1][(j & 1) * 2]);
            }
        }
        __syncthreads();   // PP tile visible before gather

        if (act) {
            // gather (2-bank rolling window) + mask + online softmax
            const int lowpar = (tjn - 1 + c) & 1;
            const float* bL = sPP + lowpar * PPBANK;
            const float* bH = sPP + (lowpar ^ 1) * PPBANK;
            const bool lastm = (c == nt_s - 1);
            float rmax0 = -1e30f, rmax1 = -1e30f;
            #pragma unroll
            for (int j = 0; j < 8; j++) {
                const int rj = 8 * j + c2;
                const int o0a = rj + 63 - row0, o0b = o0a + 1;
                const int o1a = rj + 63 - row1, o1b = o1a + 1;
                float v0 = (cl[j][0] + (o0a < 64 ? bL[row0 * PPS + o0a] : bH[row0 * PPS + o0a - 64])) * 0.125f;
                float v1 = (cl[j][1] + (o0b < 64 ? bL[row0 * PPS + o0b] : bH[row0 * PPS + o0b - 64])) * 0.125f;
                float v2 = (cl[j][2] + (o1a < 64 ? bL[row1 * PPS + o1a] : bH[row1 * PPS + o1a - 64])) * 0.125f;
                float v3 = (cl[j][3] + (o1b < 64 ? bL[row1 * PPS + o1b] : bH[row1 * PPS + o1b - 64])) * 0.125f;
                if (lastm) {
                    if (rj     > row0) v0 = -1e30f;
                    if (rj + 1 > row0) v1 = -1e30f;
                    if (rj     > row1) v2 = -1e30f;
                    if (rj + 1 > row1) v3 = -1e30f;
                }
                cl[j][0] = v0; cl[j][1] = v1; cl[j][2] = v2; cl[j][3] = v3;
                rmax0 = fmaxf(rmax0, fmaxf(v0, v1));
                rmax1 = fmaxf(rmax1, fmaxf(v2, v3));
            }
            rmax0 = fmaxf(rmax0, __shfl_xor_sync(0xffffffffu, rmax0, 1));
            rmax0 = fmaxf(rmax0, __shfl_xor_sync(0xffffffffu, rmax0, 2));
            rmax1 = fmaxf(rmax1, __shfl_xor_sync(0xffffffffu, rmax1, 1));
            rmax1 = fmaxf(rmax1, __shfl_xor_sync(0xffffffffu, rmax1, 2));
            const float mn0 = fmaxf(m0, rmax0), mn1 = fmaxf(m1, rmax1);
            const float al0 = __expf(m0 - mn0), al1 = __expf(m1 - mn1);
            m0 = mn0; m1 = mn1;

            float rs0 = 0.f, rs1 = 0.f;
            uint32_t pha[4][4], pla[4][4];
            #pragma unroll
            for (int j = 0; j < 8; j++) {
                const float p0 = __expf(cl[j][0] - mn0);
                const float p1 = __expf(cl[j][1] - mn0);
                const float p2 = __expf(cl[j][2] - mn1);
                const float p3 = __expf(cl[j][3] - mn1);
                rs0 += p0 + p1; rs1 += p2 + p3;
                const int ks = j >> 1, pos = (j & 1) * 2;
                pha[ks][pos]     = pack_split(p0, p1, pla[ks][pos]);
                pha[ks][pos + 1] = pack_split(p2, p3, pla[ks][pos + 1]);
            }
            rs0 += __shfl_xor_sync(0xffffffffu, rs0, 1);
            rs0 += __shfl_xor_sync(0xffffffffu, rs0, 2);
            rs1 += __shfl_xor_sync(0xffffffffu, rs1, 1);
            rs1 += __shfl_xor_sync(0xffffffffu, rs1, 2);
            s0 = s0 * al0 + rs0;
            s1 = s1 * al1 + rs1;

            // rescale O and accumulate P x V (3-pass)
            #pragma unroll
            for (int j = 0; j < 8; j++) {
                acc_o[j][0] *= al0; acc_o[j][1] *= al0;
                acc_o[j][2] *= al1; acc_o[j][3] *= al1;
            }
            const uint32_t vb = base + OFF_V + buf * 2 * F_T;
            #pragma unroll
            for (int ks = 0; ks < 4; ks++) {
                uint32_t bh[4][4], bl[4][4];
                #pragma unroll
                for (int jp = 0; jp < 4; jp++) {
                    const uint32_t off = SWZ128((uint32_t)((16 * jp + b_noff) * 128 + ks * 32 + b_koff));
                    ldsm_x4(bh[jp], vb + off);
                    ldsm_x4(bl[jp], vb + F_T + off);
                }
                #pragma unroll
                for (int j = 0; j < 8; j++)
                    mma16816(acc_o[j], pha[ks], &bh[j >> 1][(j & 1) * 2]);
                #pragma unroll
                for (int j = 0; j < 8; j++)
                    mma16816(acc_o[j], pha[ks], &bl[j >> 1][(j & 1) * 2]);
                #pragma unroll
                for (int j = 0; j < 8; j++)
                    mma16816(acc_o[j], pla[ks], &bh[j >> 1][(j & 1) * 2]);
            }
        }
        __syncthreads();
    }

    // epilogue: normalize and write bf16-split O
    const float inv0 = 1.f / s0, inv1 = 1.f / s1;
    #pragma unroll
    for (int j = 0; j < 8; j++) {
        const int col = h * 64 + 8 * j + c2;
        const size_t o1 = ((size_t)(b * NQ + q0s + row0)) * ND + col;
        const size_t o2 = ((size_t)(b * NQ + q0s + row1)) * ND + col;
        store_split2(&g_OH[o1], &g_OL[o1], acc_o[j][0] * inv0, acc_o[j][1] * inv0);
        store_split2(&g_OH[o2], &g_OL[o2], acc_o[j][2] * inv1, acc_o[j][3] * inv1);
    }
}

// ---------------------------------------------------------------------------
extern "C" void kernel_launch(void* const* d_in, const int* in_sizes, int n_in,
                              void* d_out, int out_size)
{
    const float* qry = (const float*)d_in[0];
    const float* mem = (const float*)d_in[1];
    const float* pe  = (const float*)d_in[2];
    const float* cb  = (const float*)d_in[4];
    const float* pb  = (const float*)d_in[5];
    const float* Wq  = (const float*)d_in[6];
    const float* Wkc = (const float*)d_in[7];
    const float* Wkp = (const float*)d_in[8];
    const float* Wv  = (const float*)d_in[9];
    const float* Wo  = (const float*)d_in[10];
    float* out = (float*)d_out;

    cudaFuncSetAttribute(mma_gemm<MODE_Q>,   cudaFuncAttributeMaxDynamicSharedMemorySize, GSMEM);
    cudaFuncSetAttribute(mma_gemm<MODE_KC>,  cudaFuncAttributeMaxDynamicSharedMemorySize, GSMEM);
    cudaFuncSetAttribute(mma_gemm<MODE_V>,   cudaFuncAttributeMaxDynamicSharedMemorySize, GSMEM);
    cudaFuncSetAttribute(mma_gemm<MODE_KP>,  cudaFuncAttributeMaxDynamicSharedMemorySize, GSMEM);
    cudaFuncSetAttribute(mma_gemm<MODE_OUT>, cudaFuncAttributeMaxDynamicSharedMemorySize, GSMEM);
    cudaFuncSetAttribute(fused_attn, cudaFuncAttributeMaxDynamicSharedMemorySize, FSMEM);

    dim3 thr(256);
    dim3 wtb(32, 8);

    // conversions
    conv_xref<<<NB * NR, 256>>>(qry, mem);
    conv_pe<<<(NR * ND) / 256, 256>>>(pe);
    conv_wt<0><<<dim3(32, 32), wtb>>>(Wq);
    conv_wt<1><<<dim3(32, 32), wtb>>>(Wkc);
    conv_wt<2><<<dim3(32, 32), wtb>>>(Wkp);
    conv_wt<3><<<dim3(32, 32), wtb>>>(Wv);
    conv_wt<4><<<dim3(32, 32), wtb>>>(Wo);

    // projections (split bf16 mma.sync)
    mma_gemm<MODE_Q ><<<dim3(8, 32), thr, GSMEM>>>(cb, pb, nullptr);
    mma_gemm<MODE_KC><<<dim3(8, 64), thr, GSMEM>>>(nullptr, nullptr, nullptr);
    mma_gemm<MODE_V ><<<dim3(8, 64), thr, GSMEM>>>(nullptr, nullptr, nullptr);
    mma_gemm<MODE_KP><<<dim3(8, 8),  thr, GSMEM>>>(nullptr, nullptr, nullptr);

    // fused flash attention: 8 warps, 128-row q-tile, shared KC/V/KP streams
    fused_attn<<<dim3(4, NB * NH), 256, FSMEM>>>();

    // output projection
    mma_gemm<MODE_OUT><<<dim3(8, 32), thr, GSMEM>>>(nullptr, nullptr, out);
}

// round 13
// speedup vs baseline: 1.0236x; 1.0236x over previous
#include <cuda_runtime.h>
#include <cuda_bf16.h>
#include <math.h>
#include <stdint.h>

// Problem constants
constexpr int NB = 8;     // batch
constexpr int NQ = 512;   // query len
constexpr int NM = 512;   // memory len
constexpr int NR = 1024;  // reference len
constexpr int NH = 16;    // heads
constexpr int NS = 64;    // size per head
constexpr int ND = 1024;  // hidden

#define ALGN __align__(16)

// bf16 split attention operands (written by projection epilogues)
__device__ ALGN __nv_bfloat16 g_QCh[(size_t)NB*NH*NQ*NS];
__device__ ALGN __nv_bfloat16 g_QCl[(size_t)NB*NH*NQ*NS];
__device__ ALGN __nv_bfloat16 g_QPh[(size_t)NB*NH*NQ*NS];
__device__ ALGN __nv_bfloat16 g_QPl[(size_t)NB*NH*NQ*NS];
__device__ ALGN __nv_bfloat16 g_KCh[(size_t)NB*NH*NR*NS];
__device__ ALGN __nv_bfloat16 g_KCl[(size_t)NB*NH*NR*NS];
__device__ ALGN __nv_bfloat16 g_KPh[(size_t)NH*NR*NS];
__device__ ALGN __nv_bfloat16 g_KPl[(size_t)NH*NR*NS];
__device__ ALGN __nv_bfloat16 g_VtH[(size_t)NB*NH*NS*NR];  // V transposed [z][s][r]
__device__ ALGN __nv_bfloat16 g_VtL[(size_t)NB*NH*NS*NR];
// attention output (bf16 split, written by fused_attn)
__device__ ALGN __nv_bfloat16 g_OH[(size_t)NB*NQ*ND];
__device__ ALGN __nv_bfloat16 g_OL[(size_t)NB*NQ*ND];

// bf16 split inputs for projections
__device__ ALGN __nv_bfloat16 g_XrefH[(size_t)NB*NR*ND];
__device__ ALGN __nv_bfloat16 g_XrefL[(size_t)NB*NR*ND];
__device__ ALGN __nv_bfloat16 g_PEH[(size_t)NR*ND];
__device__ ALGN __nv_bfloat16 g_PEL[(size_t)NR*ND];
// transposed weights Wt[c][k]: 0=Wq 1=Wkc 2=Wkp 3=Wv 4=Wo
__device__ ALGN __nv_bfloat16 g_WtH[5][(size_t)ND*ND];
__device__ ALGN __nv_bfloat16 g_WtL[5][(size_t)ND*ND];

enum { MODE_Q = 0, MODE_KC = 1, MODE_V = 2, MODE_KP = 3, MODE_OUT = 4 };

// ---------------------------------------------------------------------------
// helpers
// ---------------------------------------------------------------------------
__device__ __forceinline__ uint32_t smem_u32(const void* p) {
    uint32_t a;
    asm("{ .reg .u64 t; cvta.to.shared.u64 t, %1; cvt.u32.u64 %0, t; }"
        : "=r"(a) : "l"(p));
    return a;
}
__device__ __forceinline__ void cp16(uint32_t dst, const void* src) {
    asm volatile("cp.async.cg.shared.global [%0], [%1], 16;"
                 :: "r"(dst), "l"(src) : "memory");
}
__device__ __forceinline__ void ldsm_x4(uint32_t* r, uint32_t addr) {
    asm volatile("ldmatrix.sync.aligned.m8n8.x4.shared.b16 {%0,%1,%2,%3}, [%4];"
                 : "=r"(r[0]), "=r"(r[1]), "=r"(r[2]), "=r"(r[3]) : "r"(addr));
}
__device__ __forceinline__ void mma16816(float* c, const uint32_t* a, const uint32_t* b) {
    asm volatile(
        "mma.sync.aligned.m16n8k16.row.col.f32.bf16.bf16.f32 "
        "{%0,%1,%2,%3}, {%4,%5,%6,%7}, {%8,%9}, {%0,%1,%2,%3};"
        : "+f"(c[0]), "+f"(c[1]), "+f"(c[2]), "+f"(c[3])
        : "r"(a[0]), "r"(a[1]), "r"(a[2]), "r"(a[3]), "r"(b[0]), "r"(b[1]));
}
#define SWZ64(x)  ((x) ^ (((x) >> 3) & 0x30))
#define SWZ128(x) ((x) ^ (((x) >> 3) & 0x70))

__device__ __forceinline__ void split1(float v, __nv_bfloat16& h, __nv_bfloat16& l) {
    h = __float2bfloat16(v);
    l = __float2bfloat16(v - __bfloat162float(h));
}
__device__ __forceinline__ void store_split2(__nv_bfloat16* ph, __nv_bfloat16* pl,
                                             float a, float b) {
    __nv_bfloat162 hh, ll;
    hh.x = __float2bfloat16(a);
    ll.x = __float2bfloat16(a - __bfloat162float(hh.x));
    hh.y = __float2bfloat16(b);
    ll.y = __float2bfloat16(b - __bfloat162float(hh.y));
    *(__nv_bfloat162*)ph = hh;
    *(__nv_bfloat162*)pl = ll;
}
__device__ __forceinline__ uint32_t pack_split(float a, float b, uint32_t& lo) {
    __nv_bfloat162 hh, ll;
    hh.x = __float2bfloat16(a);
    ll.x = __float2bfloat16(a - __bfloat162float(hh.x));
    hh.y = __float2bfloat16(b);
    ll.y = __float2bfloat16(b - __bfloat162float(hh.y));
    lo = *(uint32_t*)&ll;
    return *(uint32_t*)&hh;
}

// ---------------------------------------------------------------------------
// Conversion kernels
// ---------------------------------------------------------------------------
__global__ void conv_xref(const float* __restrict__ qry, const float* __restrict__ mem) {
    const int row = blockIdx.x;
    const int b = row >> 10, r = row & 1023;
    const float* src = (r < NM) ? mem + ((size_t)(b * NM + r)) * ND
                                : qry + ((size_t)(b * NQ + (r - NM))) * ND;
    const int c = threadIdx.x * 4;
    float4 v = *(const float4*)(src + c);
    const size_t o = (size_t)row * ND + c;
    split1(v.x, g_XrefH[o+0], g_XrefL[o+0]);
    split1(v.y, g_XrefH[o+1], g_XrefL[o+1]);
    split1(v.z, g_XrefH[o+2], g_XrefL[o+2]);
    split1(v.w, g_XrefH[o+3], g_XrefL[o+3]);
}

__global__ void conv_pe(const float* __restrict__ src) {
    const size_t i = (size_t)blockIdx.x * blockDim.x + threadIdx.x;
    split1(src[i], g_PEH[i], g_PEL[i]);
}

template <int WID>
__global__ void conv_wt(const float* __restrict__ W) {
    __shared__ float tile[32][33];
    const int c0 = blockIdx.x * 32, k0 = blockIdx.y * 32;
    const int tx = threadIdx.x, ty = threadIdx.y;  // 32 x 8
    for (int i = ty; i < 32; i += 8)
        tile[i][tx] = W[(size_t)(k0 + i) * ND + c0 + tx];
    __syncthreads();
    for (int i = ty; i < 32; i += 8) {
        float v = tile[tx][i];
        __nv_bfloat16 h, l;
        split1(v, h, l);
        const size_t o = (size_t)(c0 + i) * ND + k0 + tx;
        g_WtH[WID][o] = h;
        g_WtL[WID][o] = l;
    }
}

// ---------------------------------------------------------------------------
// Split-bf16 mma.sync projection GEMM (3-pass) — unchanged (passing R11).
// ---------------------------------------------------------------------------
constexpr int TILEB  = 128 * 64;
constexpr int STAGEB = 4 * TILEB;
constexpr int GSMEM  = 2 * STAGEB + 1024;
constexpr int NCHUNK = ND / 32;

template <int MODE>
__global__ __launch_bounds__(256)
void mma_gemm(const float* __restrict__ cb, const float* __restrict__ pb,
              float* __restrict__ outp)
{
    extern __shared__ char dsm[];
    const uint32_t dyn_u32 = smem_u32(dsm);
    const uint32_t base = (dyn_u32 + 1023u) & ~1023u;
    float* stg = reinterpret_cast<float*>(dsm + (base - dyn_u32));

    const int t = threadIdx.x;
    const int wid = t >> 5, lane = t & 31;
    const int n0 = blockIdx.x * 128;
    const int m0 = blockIdx.y * 128;
    const int arow0 = (MODE == MODE_Q) ? ((m0 >> 9) * 1024 + 512 + (m0 & 511)) : m0;

    const __nv_bfloat16 *Ah, *Al, *Bh, *Bl;
    if (MODE == MODE_Q)       { Ah = g_XrefH; Al = g_XrefL; Bh = g_WtH[0]; Bl = g_WtL[0]; }
    else if (MODE == MODE_KC) { Ah = g_XrefH; Al = g_XrefL; Bh = g_WtH[1]; Bl = g_WtL[1]; }
    else if (MODE == MODE_KP) { Ah = g_PEH;   Al = g_PEL;   Bh = g_WtH[2]; Bl = g_WtL[2]; }
    else if (MODE == MODE_V)  { Ah = g_XrefH; Al = g_XrefL; Bh = g_WtH[3]; Bl = g_WtL[3]; }
    else                      { Ah = g_OH;    Al = g_OL;    Bh = g_WtH[4]; Bl = g_WtL[4]; }

    const int s0 = t;
    const int mseg0 = s0 >> 2, cseg0 = s0 & 3;
    const int s1 = t + 256;
    const int mseg1 = s1 >> 2, cseg1 = s1 & 3;

    auto load_stage = [&](int chunk, int buf) {
        const uint32_t sb = base + buf * STAGEB;
        const int kbyte = chunk * 64;
        {
            const char* a0 = (const char*)(Ah + (size_t)(arow0 + mseg0) * ND) + kbyte + cseg0 * 16;
            const char* a1 = (const char*)(Al + (size_t)(arow0 + mseg0) * ND) + kbyte + cseg0 * 16;
            const char* b0 = (const char*)(Bh + (size_t)(n0 + mseg0) * ND) + kbyte + cseg0 * 16;
            const char* b1 = (const char*)(Bl + (size_t)(n0 + mseg0) * ND) + kbyte + cseg0 * 16;
            const uint32_t sw = SWZ64((uint32_t)(mseg0 * 64 + cseg0 * 16));
            cp16(sb + 0 * TILEB + sw, a0);
            cp16(sb + 1 * TILEB + sw, a1);
            cp16(sb + 2 * TILEB + sw, b0);
            cp16(sb + 3 * TILEB + sw, b1);
        }
        {
            const char* a0 = (const char*)(Ah + (size_t)(arow0 + mseg1) * ND) + kbyte + cseg1 * 16;
            const char* a1 = (const char*)(Al + (size_t)(arow0 + mseg1) * ND) + kbyte + cseg1 * 16;
            const char* b0 = (const char*)(Bh + (size_t)(n0 + mseg1) * ND) + kbyte + cseg1 * 16;
            const char* b1 = (const char*)(Bl + (size_t)(n0 + mseg1) * ND) + kbyte + cseg1 * 16;
            const uint32_t sw = SWZ64((uint32_t)(mseg1 * 64 + cseg1 * 16));
            cp16(sb + 0 * TILEB + sw, a0);
            cp16(sb + 1 * TILEB + sw, a1);
            cp16(sb + 2 * TILEB + sw, b0);
            cp16(sb + 3 * TILEB + sw, b1);
        }
        asm volatile("cp.async.commit_group;" ::: "memory");
    };

    const int wm = wid >> 1;
    const int wn = wid & 1;
    const int mbase = wm * 32;
    const int nbase = wn * 64;

    const int tle = lane >> 3;
    const int rin = lane & 7;
    const int a_moff = rin + (tle & 1) * 8;
    const int a_koff = (tle >> 1) * 16;
    const int b_noff = (tle < 2) ? rin : (rin + 8);
    const int b_koff = (tle & 1) * 16;

    float acc[2][8][4];
    #pragma unroll
    for (int i = 0; i < 2; i++)
        #pragma unroll
        for (int j = 0; j < 8; j++)
            #pragma unroll
            for (int k = 0; k < 4; k++) acc[i][j][k] = 0.f;

    auto compute_stage = [&](int buf) {
        const uint32_t sb = base + buf * STAGEB;
        #pragma unroll
        for (int ks = 0; ks < 2; ks++) {
            uint32_t ah[2][4], al[2][4], bh[4][4], bl[4][4];
            #pragma unroll
            for (int i = 0; i < 2; i++) {
                const uint32_t off = SWZ64((uint32_t)((mbase + 16 * i + a_moff) * 64 + ks * 32 + a_koff));
                ldsm_x4(ah[i], sb + 0 * TILEB + off);
                ldsm_x4(al[i], sb + 1 * TILEB + off);
            }
            #pragma unroll
            for (int jp = 0; jp < 4; jp++) {
                const uint32_t off = SWZ64((uint32_t)((nbase + 16 * jp + b_noff) * 64 + ks * 32 + b_koff));
                ldsm_x4(bh[jp], sb + 2 * TILEB + off);
                ldsm_x4(bl[jp], sb + 3 * TILEB + off);
            }
            #pragma unroll
            for (int i = 0; i < 2; i++) {
                #pragma unroll
                for (int j = 0; j < 8; j++)
                    mma16816(acc[i][j], ah[i], &bh[j >> 1][(j & 1) * 2]);
                #pragma unroll
                for (int j = 0; j < 8; j++)
                    mma16816(acc[i][j], ah[i], &bl[j >> 1][(j & 1) * 2]);
                #pragma unroll
                for (int j = 0; j < 8; j++)
                    mma16816(acc[i][j], al[i], &bh[j >> 1][(j & 1) * 2]);
            }
        }
    };

    load_stage(0, 0);
    for (int c = 0; c < NCHUNK; c++) {
        const int buf = c & 1;
        if (c + 1 < NCHUNK) {
            load_stage(c + 1, buf ^ 1);
            asm volatile("cp.async.wait_group 1;" ::: "memory");
        } else {
            asm volatile("cp.async.wait_group 0;" ::: "memory");
        }
        __syncthreads();
        compute_stage(buf);
        __syncthreads();
    }

    const int lr = lane >> 2;
    const int lc = (lane & 3) * 2;
    for (int p = 0; p < 2; p++) {
        if ((wm >> 1) == p) {
            const int rb = mbase - p * 64;
            #pragma unroll
            for (int i = 0; i < 2; i++) {
                #pragma unroll
                for (int j = 0; j < 8; j++) {
                    const int rr = rb + 16 * i + lr;
                    const int cc = nbase + 8 * j + lc;
                    *(float2*)&stg[rr * 132 + cc]       = make_float2(acc[i][j][0], acc[i][j][1]);
                    *(float2*)&stg[(rr + 8) * 132 + cc] = make_float2(acc[i][j][2], acc[i][j][3]);
                }
            }
        }
        __syncthreads();
        if (MODE == MODE_V) {
            const int c = t >> 1;
            const int rseg = (t & 1) * 32;
            const int b = m0 >> 10;
            const int h = (n0 + c) >> 6, sO = (n0 + c) & 63;
            const int rglob0 = (m0 & 1023) + 64 * p + rseg;
            const size_t vo = (((size_t)(b * NH + h)) * NS + sO) * NR + rglob0;
            #pragma unroll 8
            for (int rl = 0; rl < 32; rl += 2) {
                store_split2(&g_VtH[vo + rl], &g_VtL[vo + rl],
                             stg[(rseg + rl) * 132 + c], stg[(rseg + rl + 1) * 132 + c]);
            }
        } else {
            const int rl = t >> 2;
            const int quad = t & 3;
            const int grow = m0 + 64 * p + rl;
            const int cq = quad * 32;
            const float* sp = stg + rl * 132 + cq;
            if (MODE == MODE_Q) {
                const int b = grow >> 9, q = grow & 511;
                const int h = (n0 + cq) >> 6, sO = (n0 + cq) & 63;
                const size_t o = (((size_t)(b * NH + h)) * NQ + q) * NS + sO;
                const float* cbp = cb + n0 + cq;
                const float* pbp = pb + n0 + cq;
                #pragma unroll
                for (int j = 0; j < 32; j += 2) {
                    const float v0 = sp[j], v1 = sp[j + 1];
                    store_split2(&g_QCh[o + j], &g_QCl[o + j], v0 + cbp[j], v1 + cbp[j + 1]);
                    store_split2(&g_QPh[o + j], &g_QPl[o + j], v0 + pbp[j], v1 + pbp[j + 1]);
                }
            } else if (MODE == MODE_KC) {
                const int b = grow >> 10, r = grow & 1023;
                const int h = (n0 + cq) >> 6, sO = (n0 + cq) & 63;
                const size_t o = (((size_t)(b * NH + h)) * NR + r) * NS + sO;
                #pragma unroll
                for (int j = 0; j < 32; j += 2)
                    store_split2(&g_KCh[o + j], &g_KCl[o + j], sp[j], sp[j + 1]);
            } else if (MODE == MODE_KP) {
                const int h = (n0 + cq) >> 6, sO = (n0 + cq) & 63;
                const size_t o = ((size_t)h * NR + grow) * NS + sO;
                #pragma unroll
                for (int j = 0; j < 32; j += 2)
                    store_split2(&g_KPh[o + j], &g_KPl[o + j], sp[j], sp[j + 1]);
            } else {
                float* d1 = outp + (size_t)grow * ND + n0 + cq;
                #pragma unroll
                for (int j = 0; j < 32; j += 4)
                    *(float4*)(d1 + j) = make_float4(sp[j], sp[j+1], sp[j+2], sp[j+3]);
            }
        }
        __syncthreads();
    }
}

// ---------------------------------------------------------------------------
// fused_attn (R11 base, barrier-minimized):
//  - PP band is warp-private -> pre-gather sync is __syncwarp only
//  - KP ring = 3 slots, prefetch issued AFTER the single top-of-iter
//    __syncthreads -> trailing barrier removed entirely.
// One block barrier per iteration (was three).
// ---------------------------------------------------------------------------
constexpr int F_T    = 8192;           // one 64x128B tile
constexpr int OFF_Q  = 0;              // QCh,QCl,QPh,QPl
constexpr int OFF_KC = 4 * F_T;        // 2 bufs x (h,l)
constexpr int OFF_V  = 8 * F_T;        // 2 bufs x (h,l)
constexpr int OFF_KP = 12 * F_T;       // 3 slots x (h,l)
constexpr int OFF_PP = 18 * F_T;       // 2 banks x 64 x 66 fp32
constexpr int PPS    = 66;
constexpr int PPBANK = 64 * PPS;       // floats per bank
constexpr int FSMEM  = OFF_PP + 2 * PPBANK * 4 + 1024;

__global__ __launch_bounds__(128)
void fused_attn()
{
    extern __shared__ char fsm[];
    const uint32_t raw = smem_u32(fsm);
    const uint32_t base = (raw + 1023u) & ~1023u;
    float* sPP = reinterpret_cast<float*>(fsm + (base - raw) + OFF_PP);

    const int qt = blockIdx.x;
    const int z  = blockIdx.y;
    const int q0 = qt * 64;
    const int b = z >> 4, h = z & 15;
    const int nt = qt + 9;
    const int tj0 = 7 - qt;

    const int t = threadIdx.x;
    const int wid = t >> 5, lane = t & 31;
    const int mrow = wid * 16;

    const char* QCh = (const char*)(g_QCh + ((size_t)z * NQ + q0) * NS);
    const char* QCl = (const char*)(g_QCl + ((size_t)z * NQ + q0) * NS);
    const char* QPh = (const char*)(g_QPh + ((size_t)z * NQ + q0) * NS);
    const char* QPl = (const char*)(g_QPl + ((size_t)z * NQ + q0) * NS);
    const char* KCh = (const char*)(g_KCh + (size_t)z * NR * NS);
    const char* KCl = (const char*)(g_KCl + (size_t)z * NR * NS);
    const char* KPh = (const char*)(g_KPh + (size_t)h * NR * NS);
    const char* KPl = (const char*)(g_KPl + (size_t)h * NR * NS);
    const char* Vh  = (const char*)(g_VtH + (size_t)z * NS * NR);
    const char* Vl  = (const char*)(g_VtL + (size_t)z * NS * NR);

    auto load_kcv = [&](int c, int buf) {
        const uint32_t kb = base + OFF_KC + buf * 2 * F_T;
        const uint32_t vb = base + OFF_V  + buf * 2 * F_T;
        #pragma unroll
        for (int i = 0; i < 4; i++) {
            const int idx = t + 128 * i;
            const int row = idx >> 3, c16 = idx & 7;
            const uint32_t sw = SWZ128((uint32_t)(row * 128 + c16 * 16));
            const size_t kco = (size_t)(c * 64 + row) * 128 + c16 * 16;
            cp16(kb + sw,        KCh + kco);
            cp16(kb + F_T + sw,  KCl + kco);
            const size_t vo = (size_t)row * (NR * 2) + (size_t)c * 128 + c16 * 16;
            cp16(vb + sw,        Vh + vo);
            cp16(vb + F_T + sw,  Vl + vo);
        }
    };
    auto load_kp = [&](int tj) {
        const int slot = tj % 3;
        const uint32_t kb = base + OFF_KP + slot * 2 * F_T;
        #pragma unroll
        for (int i = 0; i < 4; i++) {
            const int idx = t + 128 * i;
            const int row = idx >> 3, c16 = idx & 7;
            int k = tj * 64 + row;
            if (k > 1023) k = 1023;               // clamped rows feed masked lanes only
            const uint32_t sw = SWZ128((uint32_t)(row * 128 + c16 * 16));
            cp16(kb + sw,       KPh + (size_t)k * 128 + c16 * 16);
            cp16(kb + F_T + sw, KPl + (size_t)k * 128 + c16 * 16);
        }
    };

    // prologue loads: Q tiles + first KC/V + KP tiles tj0, tj0+1
    #pragma unroll
    for (int i = 0; i < 4; i++) {
        const int idx = t + 128 * i;
        const int row = idx >> 3, c16 = idx & 7;
        const uint32_t sw = SWZ128((uint32_t)(row * 128 + c16 * 16));
        const size_t qo = (size_t)row * 128 + c16 * 16;
        cp16(base + OFF_Q + 0 * F_T + sw, QCh + qo);
        cp16(base + OFF_Q + 1 * F_T + sw, QCl + qo);
        cp16(base + OFF_Q + 2 * F_T + sw, QPh + qo);
        cp16(base + OFF_Q + 3 * F_T + sw, QPl + qo);
    }
    load_kcv(0, 0);
    load_kp(tj0);
    load_kp(tj0 + 1);
    asm volatile("cp.async.commit_group;" ::: "memory");
    asm volatile("cp.async.wait_group 0;" ::: "memory");
    __syncthreads();

    const int tle = lane >> 3;
    const int rin = lane & 7;
    const int a_moff = rin + (tle & 1) * 8;
    const int a_koff = (tle >> 1) * 16;
    const int b_noff = (tle < 2) ? rin : (rin + 8);
    const int b_koff = (tle & 1) * 16;
    const int r_ = lane >> 2;
    const int c2 = (lane & 3) * 2;
    const int row0 = mrow + r_;
    const int row1 = row0 + 8;

    // preload Q a-frags (persistent)
    uint32_t qch[4][4], qcl[4][4], qph[4][4], qpl[4][4];
    #pragma unroll
    for (int ks = 0; ks < 4; ks++) {
        const uint32_t off = SWZ128((uint32_t)((mrow + a_moff) * 128 + ks * 32 + a_koff));
        ldsm_x4(qch[ks], base + OFF_Q + 0 * F_T + off);
        ldsm_x4(qcl[ks], base + OFF_Q + 1 * F_T + off);
        ldsm_x4(qph[ks], base + OFF_Q + 2 * F_T + off);
        ldsm_x4(qpl[ks], base + OFF_Q + 3 * F_T + off);
    }

    // compute one PP tile (3-pass) from KP slot tj%3 into PP bank tj&1.
    // PP rows are warp-private: only __syncwarp needed before gather.
    auto pp_tile = [&](int tj) {
        const uint32_t kb = base + OFF_KP + (tj % 3) * 2 * F_T;
        float pa[8][4];
        #pragma unroll
        for (int j = 0; j < 8; j++)
            #pragma unroll
            for (int e = 0; e < 4; e++) pa[j][e] = 0.f;
        #pragma unroll
        for (int ks = 0; ks < 4; ks++) {
            uint32_t bh[4][4], bl[4][4];
            #pragma unroll
            for (int jp = 0; jp < 4; jp++) {
                const uint32_t off = SWZ128((uint32_t)((16 * jp + b_noff) * 128 + ks * 32 + b_koff));
                ldsm_x4(bh[jp], kb + off);
                ldsm_x4(bl[jp], kb + F_T + off);
            }
            #pragma unroll
            for (int j = 0; j < 8; j++)
                mma16816(pa[j], qph[ks], &bh[j >> 1][(j & 1) * 2]);
            #pragma unroll
            for (int j = 0; j < 8; j++)
                mma16816(pa[j], qph[ks], &bl[j >> 1][(j & 1) * 2]);
            #pragma unroll
            for (int j = 0; j < 8; j++)
                mma16816(pa[j], qpl[ks], &bh[j >> 1][(j & 1) * 2]);
        }
        float* bw = sPP + (tj & 1) * PPBANK;
        #pragma unroll
        for (int j = 0; j < 8; j++) {
            const int col = 8 * j + c2;
            *(float2*)&bw[row0 * PPS + col] = make_float2(pa[j][0], pa[j][1]);
            *(float2*)&bw[row1 * PPS + col] = make_float2(pa[j][2], pa[j][3]);
        }
    };

    // prologue PP: tile T(0) = tj0 (3-slot ring: iter-0 prefetch won't touch it)
    pp_tile(tj0);

    float m0 = -1e30f, m1 = -1e30f, s0 = 0.f, s1 = 0.f;
    float acc_o[8][4];
    #pragma unroll
    for (int j = 0; j < 8; j++)
        #pragma unroll
        for (int e = 0; e < 4; e++) acc_o[j][e] = 0.f;

    for (int c = 0; c < nt; c++) {
        const int buf = c & 1;
        // wait for this iteration's data (committed last iteration / prologue)
        asm volatile("cp.async.wait_group 0;" ::: "memory");
        __syncthreads();   // single block barrier: prev-iter reads all done

        // prefetch next iteration (safe: targets buf^1 and KP slot (tj0+c+2)%3,
        // whose previous readers finished before the barrier above)
        if (c + 1 < nt) {
            load_kcv(c + 1, buf ^ 1);
            load_kp(tj0 + c + 2);
            asm volatile("cp.async.commit_group;" ::: "memory");
        }

        // --- new positional tile T(c+1) (warp-private output) ---
        pp_tile(tj0 + c + 1);

        // --- content logits (3-pass, K=64) ---
        float cl[8][4];
        #pragma unroll
        for (int j = 0; j < 8; j++)
            #pragma unroll
            for (int e = 0; e < 4; e++) cl[j][e] = 0.f;
        {
            const uint32_t kb = base + OFF_KC + buf * 2 * F_T;
            #pragma unroll
            for (int ks = 0; ks < 4; ks++) {
                uint32_t bh[4][4], bl[4][4];
                #pragma unroll
                for (int jp = 0; jp < 4; jp++) {
                    const uint32_t off = SWZ128((uint32_t)((16 * jp + b_noff) * 128 + ks * 32 + b_koff));
                    ldsm_x4(bh[jp], kb + off);
                    ldsm_x4(bl[jp], kb + F_T + off);
                }
                #pragma unroll
                for (int j = 0; j < 8; j++)
                    mma16816(cl[j], qch[ks], &bh[j >> 1][(j & 1) * 2]);
                #pragma unroll
                for (int j = 0; j < 8; j++)
                    mma16816(cl[j], qch[ks], &bl[j >> 1][(j & 1) * 2]);
                #pragma unroll
                for (int j = 0; j < 8; j++)
                    mma16816(cl[j], qcl[ks], &bh[j >> 1][(j & 1) * 2]);
            }
        }
        __syncwarp();   // PP writes (same warp) visible before gather

        // --- gather (2-bank rolling window) + mask + online softmax ---
        const int lowpar = (tj0 + c) & 1;
        const float* bL = sPP + lowpar * PPBANK;
        const float* bH = sPP + (lowpar ^ 1) * PPBANK;
        const bool last = (c == nt - 1);
        float rmax0 = -1e30f, rmax1 = -1e30f;
        #pragma unroll
        for (int j = 0; j < 8; j++) {
            const int rj = 8 * j + c2;
            const int o0a = rj + 63 - row0, o0b = o0a + 1;
            const int o1a = rj + 63 - row1, o1b = o1a + 1;
            float v0 = (cl[j][0] + (o0a < 64 ? bL[row0 * PPS + o0a] : bH[row0 * PPS + o0a - 64])) * 0.125f;
            float v1 = (cl[j][1] + (o0b < 64 ? bL[row0 * PPS + o0b] : bH[row0 * PPS + o0b - 64])) * 0.125f;
            float v2 = (cl[j][2] + (o1a < 64 ? bL[row1 * PPS + o1a] : bH[row1 * PPS + o1a - 64])) * 0.125f;
            float v3 = (cl[j][3] + (o1b < 64 ? bL[row1 * PPS + o1b] : bH[row1 * PPS + o1b - 64])) * 0.125f;
            if (last) {
                if (rj     > row0) v0 = -1e30f;
                if (rj + 1 > row0) v1 = -1e30f;
                if (rj     > row1) v2 = -1e30f;
                if (rj + 1 > row1) v3 = -1e30f;
            }
            cl[j][0] = v0; cl[j][1] = v1; cl[j][2] = v2; cl[j][3] = v3;
            rmax0 = fmaxf(rmax0, fmaxf(v0, v1));
            rmax1 = fmaxf(rmax1, fmaxf(v2, v3));
        }
        rmax0 = fmaxf(rmax0, __shfl_xor_sync(0xffffffffu, rmax0, 1));
        rmax0 = fmaxf(rmax0, __shfl_xor_sync(0xffffffffu, rmax0, 2));
        rmax1 = fmaxf(rmax1, __shfl_xor_sync(0xffffffffu, rmax1, 1));
        rmax1 = fmaxf(rmax1, __shfl_xor_sync(0xffffffffu, rmax1, 2));
        const float mn0 = fmaxf(m0, rmax0), mn1 = fmaxf(m1, rmax1);
        const float al0 = __expf(m0 - mn0), al1 = __expf(m1 - mn1);
        m0 = mn0; m1 = mn1;

        float rs0 = 0.f, rs1 = 0.f;
        uint32_t pha[4][4], pla[4][4];
        #pragma unroll
        for (int j = 0; j < 8; j++) {
            const float p0 = __expf(cl[j][0] - mn0);
            const float p1 = __expf(cl[j][1] - mn0);
            const float p2 = __expf(cl[j][2] - mn1);
            const float p3 = __expf(cl[j][3] - mn1);
            rs0 += p0 + p1; rs1 += p2 + p3;
            const int ks = j >> 1, pos = (j & 1) * 2;
            pha[ks][pos]     = pack_split(p0, p1, pla[ks][pos]);
            pha[ks][pos + 1] = pack_split(p2, p3, pla[ks][pos + 1]);
        }
        rs0 += __shfl_xor_sync(0xffffffffu, rs0, 1);
        rs0 += __shfl_xor_sync(0xffffffffu, rs0, 2);
        rs1 += __shfl_xor_sync(0xffffffffu, rs1, 1);
        rs1 += __shfl_xor_sync(0xffffffffu, rs1, 2);
        s0 = s0 * al0 + rs0;
        s1 = s1 * al1 + rs1;

        // rescale O and accumulate P x V (3-pass)
        #pragma unroll
        for (int j = 0; j < 8; j++) {
            acc_o[j][0] *= al0; acc_o[j][1] *= al0;
            acc_o[j][2] *= al1; acc_o[j][3] *= al1;
        }
        {
            const uint32_t vb = base + OFF_V + buf * 2 * F_T;
            #pragma unroll
            for (int ks = 0; ks < 4; ks++) {
                uint32_t bh[4][4], bl[4][4];
                #pragma unroll
                for (int jp = 0; jp < 4; jp++) {
                    const uint32_t off = SWZ128((uint32_t)((16 * jp + b_noff) * 128 + ks * 32 + b_koff));
                    ldsm_x4(bh[jp], vb + off);
                    ldsm_x4(bl[jp], vb + F_T + off);
                }
                #pragma unroll
                for (int j = 0; j < 8; j++)
                    mma16816(acc_o[j], pha[ks], &bh[j >> 1][(j & 1) * 2]);
                #pragma unroll
                for (int j = 0; j < 8; j++)
                    mma16816(acc_o[j], pha[ks], &bl[j >> 1][(j & 1) * 2]);
                #pragma unroll
                for (int j = 0; j < 8; j++)
                    mma16816(acc_o[j], pla[ks], &bh[j >> 1][(j & 1) * 2]);
            }
        }
        // no trailing block barrier: next iteration's top barrier handles WAR
    }

    // epilogue: normalize and write bf16-split O
    const float inv0 = 1.f / s0, inv1 = 1.f / s1;
    #pragma unroll
    for (int j = 0; j < 8; j++) {
        const int col = h * 64 + 8 * j + c2;
        const size_t o1 = ((size_t)(b * NQ + q0 + row0)) * ND + col;
        const size_t o2 = ((size_t)(b * NQ + q0 + row1)) * ND + col;
        store_split2(&g_OH[o1], &g_OL[o1], acc_o[j][0] * inv0, acc_o[j][1] * inv0);
        store_split2(&g_OH[o2], &g_OL[o2], acc_o[j][2] * inv1, acc_o[j][3] * inv1);
    }
}

// ---------------------------------------------------------------------------
extern "C" void kernel_launch(void* const* d_in, const int* in_sizes, int n_in,
                              void* d_out, int out_size)
{
    const float* qry = (const float*)d_in[0];
    const float* mem = (const float*)d_in[1];
    const float* pe  = (const float*)d_in[2];
    const float* cb  = (const float*)d_in[4];
    const float* pb  = (const float*)d_in[5];
    const float* Wq  = (const float*)d_in[6];
    const float* Wkc = (const float*)d_in[7];
    const float* Wkp = (const float*)d_in[8];
    const float* Wv  = (const float*)d_in[9];
    const float* Wo  = (const float*)d_in[10];
    float* out = (float*)d_out;

    cudaFuncSetAttribute(mma_gemm<MODE_Q>,   cudaFuncAttributeMaxDynamicSharedMemorySize, GSMEM);
    cudaFuncSetAttribute(mma_gemm<MODE_KC>,  cudaFuncAttributeMaxDynamicSharedMemorySize, GSMEM);
    cudaFuncSetAttribute(mma_gemm<MODE_V>,   cudaFuncAttributeMaxDynamicSharedMemorySize, GSMEM);
    cudaFuncSetAttribute(mma_gemm<MODE_KP>,  cudaFuncAttributeMaxDynamicSharedMemorySize, GSMEM);
    cudaFuncSetAttribute(mma_gemm<MODE_OUT>, cudaFuncAttributeMaxDynamicSharedMemorySize, GSMEM);
    cudaFuncSetAttribute(fused_attn, cudaFuncAttributeMaxDynamicSharedMemorySize, FSMEM);

    dim3 thr(256);
    dim3 wtb(32, 8);

    // conversions
    conv_xref<<<NB * NR, 256>>>(qry, mem);
    conv_pe<<<(NR * ND) / 256, 256>>>(pe);
    conv_wt<0><<<dim3(32, 32), wtb>>>(Wq);
    conv_wt<1><<<dim3(32, 32), wtb>>>(Wkc);
    conv_wt<2><<<dim3(32, 32), wtb>>>(Wkp);
    conv_wt<3><<<dim3(32, 32), wtb>>>(Wv);
    conv_wt<4><<<dim3(32, 32), wtb>>>(Wo);

    // projections (split bf16 mma.sync)
    mma_gemm<MODE_Q ><<<dim3(8, 32), thr, GSMEM>>>(cb, pb, nullptr);
    mma_gemm<MODE_KC><<<dim3(8, 64), thr, GSMEM>>>(nullptr, nullptr, nullptr);
    mma_gemm<MODE_V ><<<dim3(8, 64), thr, GSMEM>>>(nullptr, nullptr, nullptr);
    mma_gemm<MODE_KP><<<dim3(8, 8),  thr, GSMEM>>>(nullptr, nullptr, nullptr);

    // fused flash attention (score + rel-shift + softmax + P*V, 1 barrier/iter)
    fused_attn<<<dim3(8, NB * NH), 128, FSMEM>>>();

    // output projection
    mma_gemm<MODE_OUT><<<dim3(8, 32), thr, GSMEM>>>(nullptr, nullptr, out);
}